// round 1
// baseline (speedup 1.0000x reference)
#include <cuda_runtime.h>
#include <math.h>

#define N_BATCH 4
#define C_DIM   512
#define L_DIM   4096           // 64*64
#define NGROUP  32
#define CPG     (C_DIM / NGROUP)   // 16
#define GN_EPS  1e-5f
#define CL      ((size_t)C_DIM * L_DIM)        // 2,097,152
#define LL      ((size_t)L_DIM * L_DIM)        // 16,777,216

// ---------------- scratch (static device globals; no allocation) ----------------
__device__ float g_h[N_BATCH * CL];   // groupnorm output, per-batch [C, L]
__device__ float g_q[N_BATCH * CL];
__device__ float g_k[N_BATCH * CL];
__device__ float g_v[N_BATCH * CL];
__device__ float g_o[N_BATCH * CL];   // att @ v
__device__ float g_s[N_BATCH * LL];   // scores / attention probs [L, L] per batch

// ---------------- GroupNorm: one block per (n, group) ----------------
__global__ void gn_kernel(const float* __restrict__ x,
                          const float* __restrict__ scale,
                          const float* __restrict__ bias)
{
    const int n = blockIdx.x / NGROUP;
    const int g = blockIdx.x % NGROUP;
    const size_t base = ((size_t)n * C_DIM + (size_t)g * CPG) * L_DIM;
    const float* __restrict__ xp = x + base;
    float* __restrict__ hp = g_h + base;

    const int nelem = CPG * L_DIM;   // 65536
    float s = 0.f, ss = 0.f;
    for (int i = threadIdx.x; i < nelem; i += blockDim.x) {
        float v = xp[i];
        s  += v;
        ss += v * v;
    }
    __shared__ float rs[256], rss[256];
    rs[threadIdx.x]  = s;
    rss[threadIdx.x] = ss;
    __syncthreads();
    for (int st = 128; st > 0; st >>= 1) {
        if (threadIdx.x < st) {
            rs[threadIdx.x]  += rs[threadIdx.x + st];
            rss[threadIdx.x] += rss[threadIdx.x + st];
        }
        __syncthreads();
    }
    const float inv_n = 1.f / (float)nelem;
    const float mean = rs[0] * inv_n;
    const float var  = rss[0] * inv_n - mean * mean;
    const float rstd = rsqrtf(var + GN_EPS);

    for (int i = threadIdx.x; i < nelem; i += blockDim.x) {
        int c = g * CPG + (i >> 12);   // i / 4096
        hp[i] = (xp[i] - mean) * rstd * scale[c] + bias[c];
    }
}

// ---------------- Tiled SGEMM, templated on operand transposes ----------------
// C[m,n] = alpha * sum_k a(m,k)*b(k,n) + bias[m] (+ res[m,n])
//   a(m,k) = TA ? A[k*M + m] : A[m*K + k]
//   b(k,n) = TB ? B[n*K + k] : B[k*N + n]
// Requires M % 64 == 0, N % 64 == 0, K % 16 == 0.  blockDim = 256.
template <int TA, int TB>
__global__ __launch_bounds__(256)
void sgemm_kernel(const float* __restrict__ A, const float* __restrict__ B,
                  float* __restrict__ C, int M, int N, int K, float alpha,
                  const float* __restrict__ bias, const float* __restrict__ res)
{
    constexpr int BM = 64, BN = 64, BK = 16;
    __shared__ float As[BK][BM + 4];
    __shared__ float Bs[BK][BN + 4];

    const int tid = threadIdx.x;
    const int tx = tid & 15;          // 0..15 -> n subtile
    const int ty = tid >> 4;          // 0..15 -> m subtile
    const int bm = blockIdx.y * BM;
    const int bn = blockIdx.x * BN;

    float acc[4][4] = {};

    for (int k0 = 0; k0 < K; k0 += BK) {
        // load A tile (BK x BM = 1024 elems, 4 per thread)
        #pragma unroll
        for (int i = 0; i < 4; i++) {
            int idx = tid + i * 256;
            int kk, mm;
            if (TA) { mm = idx & (BM - 1); kk = idx >> 6; }   // A[k*M+m]: m contiguous
            else    { kk = idx & (BK - 1); mm = idx >> 4; }   // A[m*K+k]: k contiguous
            int m = bm + mm, k = k0 + kk;
            As[kk][mm] = TA ? A[(size_t)k * M + m] : A[(size_t)m * K + k];
        }
        // load B tile
        #pragma unroll
        for (int i = 0; i < 4; i++) {
            int idx = tid + i * 256;
            int kk, nn;
            if (TB) { kk = idx & (BK - 1); nn = idx >> 4; }   // B[n*K+k]: k contiguous
            else    { nn = idx & (BN - 1); kk = idx >> 6; }   // B[k*N+n]: n contiguous
            int n = bn + nn, k = k0 + kk;
            Bs[kk][nn] = TB ? B[(size_t)n * K + k] : B[(size_t)k * N + n];
        }
        __syncthreads();

        #pragma unroll
        for (int kk = 0; kk < BK; kk++) {
            float4 av = *reinterpret_cast<const float4*>(&As[kk][ty * 4]);
            float4 bv = *reinterpret_cast<const float4*>(&Bs[kk][tx * 4]);
            float a[4] = {av.x, av.y, av.z, av.w};
            float b[4] = {bv.x, bv.y, bv.z, bv.w};
            #pragma unroll
            for (int i = 0; i < 4; i++)
                #pragma unroll
                for (int j = 0; j < 4; j++)
                    acc[i][j] += a[i] * b[j];
        }
        __syncthreads();
    }

    #pragma unroll
    for (int i = 0; i < 4; i++) {
        int m = bm + ty * 4 + i;
        float bv = bias ? bias[m] : 0.f;
        #pragma unroll
        for (int j = 0; j < 4; j++) {
            int n = bn + tx * 4 + j;
            float v = alpha * acc[i][j] + bv;
            if (res) v += res[(size_t)m * N + n];
            C[(size_t)m * N + n] = v;
        }
    }
}

// ---------------- Row softmax: one block per row of 4096 ----------------
__global__ void softmax_kernel(float* __restrict__ s)
{
    float* __restrict__ row = s + (size_t)blockIdx.x * L_DIM;
    __shared__ float red[256];

    float m = -INFINITY;
    for (int i = threadIdx.x; i < L_DIM; i += 256)
        m = fmaxf(m, row[i]);
    red[threadIdx.x] = m;
    __syncthreads();
    for (int st = 128; st > 0; st >>= 1) {
        if (threadIdx.x < st)
            red[threadIdx.x] = fmaxf(red[threadIdx.x], red[threadIdx.x + st]);
        __syncthreads();
    }
    m = red[0];
    __syncthreads();

    float sum = 0.f;
    for (int i = threadIdx.x; i < L_DIM; i += 256) {
        float e = __expf(row[i] - m);
        row[i] = e;
        sum += e;
    }
    red[threadIdx.x] = sum;
    __syncthreads();
    for (int st = 128; st > 0; st >>= 1) {
        if (threadIdx.x < st)
            red[threadIdx.x] += red[threadIdx.x + st];
        __syncthreads();
    }
    const float inv = 1.f / red[0];
    for (int i = threadIdx.x; i < L_DIM; i += 256)
        row[i] *= inv;
}

// ---------------- host launch ----------------
extern "C" void kernel_launch(void* const* d_in, const int* in_sizes, int n_in,
                              void* d_out, int out_size)
{
    const float* x        = (const float*)d_in[0];
    const float* gn_scale = (const float*)d_in[1];
    const float* gn_bias  = (const float*)d_in[2];
    const float* wq = (const float*)d_in[3];
    const float* bq = (const float*)d_in[4];
    const float* wk = (const float*)d_in[5];
    const float* bk = (const float*)d_in[6];
    const float* wv = (const float*)d_in[7];
    const float* bv = (const float*)d_in[8];
    const float* wo = (const float*)d_in[9];
    const float* bo = (const float*)d_in[10];
    float* out = (float*)d_out;

    static float *p_h = nullptr, *p_q = nullptr, *p_k = nullptr,
                 *p_v = nullptr, *p_o = nullptr, *p_s = nullptr;
    if (!p_h) {
        cudaGetSymbolAddress((void**)&p_h, g_h);
        cudaGetSymbolAddress((void**)&p_q, g_q);
        cudaGetSymbolAddress((void**)&p_k, g_k);
        cudaGetSymbolAddress((void**)&p_v, g_v);
        cudaGetSymbolAddress((void**)&p_o, g_o);
        cudaGetSymbolAddress((void**)&p_s, g_s);
    }

    const float att_scale = 0.044194173824159216f;  // 512^-0.5

    // 1. GroupNorm -> g_h
    gn_kernel<<<N_BATCH * NGROUP, 256>>>(x, gn_scale, gn_bias);

    // 2. QKV projections: [512,512] x [512,4096] per batch
    {
        dim3 grid(L_DIM / 64, C_DIM / 64);   // (64, 8)
        for (int n = 0; n < N_BATCH; n++) {
            const float* hn = p_h + n * CL;
            sgemm_kernel<0,0><<<grid, 256>>>(wq, hn, p_q + n * CL,
                                             C_DIM, L_DIM, C_DIM, 1.f, bq, nullptr);
            sgemm_kernel<0,0><<<grid, 256>>>(wk, hn, p_k + n * CL,
                                             C_DIM, L_DIM, C_DIM, 1.f, bk, nullptr);
            sgemm_kernel<0,0><<<grid, 256>>>(wv, hn, p_v + n * CL,
                                             C_DIM, L_DIM, C_DIM, 1.f, bv, nullptr);
        }
    }

    // 3. scores = q^T k * scale : [4096,4096], K=512
    {
        dim3 grid(L_DIM / 64, L_DIM / 64);   // (64, 64)
        for (int n = 0; n < N_BATCH; n++)
            sgemm_kernel<1,0><<<grid, 256>>>(p_q + n * CL, p_k + n * CL, p_s + n * LL,
                                             L_DIM, L_DIM, C_DIM, att_scale,
                                             nullptr, nullptr);
    }

    // 4. softmax over last dim, all rows of all batches
    softmax_kernel<<<N_BATCH * L_DIM, 256>>>(p_s);

    // 5. out = v @ att^T : [512,4096], K=4096
    {
        dim3 grid(L_DIM / 64, C_DIM / 64);
        for (int n = 0; n < N_BATCH; n++)
            sgemm_kernel<0,1><<<grid, 256>>>(p_v + n * CL, p_s + n * LL, p_o + n * CL,
                                             C_DIM, L_DIM, L_DIM, 1.f,
                                             nullptr, nullptr);
    }

    // 6. final projection + bias + residual
    {
        dim3 grid(L_DIM / 64, C_DIM / 64);
        for (int n = 0; n < N_BATCH; n++)
            sgemm_kernel<0,0><<<grid, 256>>>(wo, p_o + n * CL, out + n * CL,
                                             C_DIM, L_DIM, C_DIM, 1.f, bo, x + n * CL);
    }
}

// round 2
// speedup vs baseline: 4.0478x; 4.0478x over previous
#include <cuda_runtime.h>
#include <math.h>
#include <stdint.h>

#define N_BATCH 4
#define C_DIM   512
#define L_DIM   4096
#define NGROUP  32
#define CPG     16
#define GN_EPS  1e-5f
#define CL      ((size_t)C_DIM * L_DIM)
#define LL      ((size_t)L_DIM * L_DIM)

// ---------------- scratch ----------------
__device__ float g_ht[N_BATCH * CL];  // groupnorm output, [L, C] per batch
__device__ float g_q[N_BATCH * CL];   // [L, C]
__device__ float g_k[N_BATCH * CL];   // [L, C]
__device__ float g_v[N_BATCH * CL];   // [C, L]
__device__ float g_o[N_BATCH * CL];   // att @ v, [L, C]
__device__ float g_s[N_BATCH * LL];   // scores / probs [L, L]

// ---------------- GroupNorm -> transposed output h_t[L, C] ----------------
__global__ __launch_bounds__(256) void gn_kernel(const float* __restrict__ x,
                                                 const float* __restrict__ scale,
                                                 const float* __restrict__ bias,
                                                 float* __restrict__ ht)
{
    const int n = blockIdx.x >> 5;
    const int g = blockIdx.x & 31;
    const float* __restrict__ xg = x + ((size_t)n * C_DIM + (size_t)g * CPG) * L_DIM;
    float* __restrict__ hb = ht + (size_t)n * CL + g * CPG;
    const int tid = threadIdx.x;

    // stats over 16 x 4096
    const float4* xv = (const float4*)xg;
    float s = 0.f, ss = 0.f;
    for (int i = tid; i < CPG * L_DIM / 4; i += 256) {
        float4 v = xv[i];
        s  += v.x + v.y + v.z + v.w;
        ss += v.x*v.x + v.y*v.y + v.z*v.z + v.w*v.w;
    }
    __shared__ float rs[256], rss[256];
    rs[tid] = s; rss[tid] = ss;
    __syncthreads();
    for (int st = 128; st > 0; st >>= 1) {
        if (tid < st) { rs[tid] += rs[tid+st]; rss[tid] += rss[tid+st]; }
        __syncthreads();
    }
    const float inv_n = 1.f / (float)(CPG * L_DIM);
    const float mean = rs[0] * inv_n;
    const float var  = rss[0] * inv_n - mean * mean;
    const float rstd = rsqrtf(var + GN_EPS);

    __shared__ float tile[16][260];
    for (int l0 = 0; l0 < L_DIM; l0 += 256) {
        #pragma unroll
        for (int j = 0; j < 4; j++) {
            int vi = tid + j * 256;
            int c  = vi >> 6;       // 0..15
            int lv = vi & 63;       // float4 index within 256 l's
            float4 v = xv[c * (L_DIM/4) + (l0 >> 2) + lv];
            float sc = scale[g*CPG + c] * rstd;
            float bi = bias[g*CPG + c] - mean * sc;
            tile[c][4*lv+0] = v.x*sc + bi;
            tile[c][4*lv+1] = v.y*sc + bi;
            tile[c][4*lv+2] = v.z*sc + bi;
            tile[c][4*lv+3] = v.w*sc + bi;
        }
        __syncthreads();
        #pragma unroll
        for (int j = 0; j < 4; j++) {
            int vi = tid + j * 256;
            int l  = vi >> 2;
            int c4 = vi & 3;
            float4 o;
            o.x = tile[4*c4+0][l];
            o.y = tile[4*c4+1][l];
            o.z = tile[4*c4+2][l];
            o.w = tile[4*c4+3][l];
            *(float4*)&hb[(size_t)(l0 + l) * C_DIM + 4*c4] = o;
        }
        __syncthreads();
    }
}

// ---------------- tf32 MMA NT-GEMM ----------------
// C[M,N] = alpha * A[M,K] * B[N,K]^T + bias[n] (+ res); both operands K-major.
#define BM 128
#define BN 128
#define BK 32
#define ROWF 36                    // smem floats per row (32 + 4 pad -> conflict-free)
#define TILEF (128 * ROWF)         // 4608 floats
#define SMEM_BYTES (4 * TILEF * 4) // 2 stages x (A + B) = 73728 B

__device__ __forceinline__ uint32_t f2tf(float f) {
    uint32_t r;
    asm("cvt.rna.tf32.f32 %0, %1;" : "=r"(r) : "f"(f));
    return r;
}

__device__ __forceinline__ void mma_tf32(float* d, const uint32_t* a, const uint32_t* b) {
    asm volatile(
        "mma.sync.aligned.m16n8k8.row.col.f32.tf32.tf32.f32 "
        "{%0,%1,%2,%3},{%4,%5,%6,%7},{%8,%9},{%0,%1,%2,%3};"
        : "+f"(d[0]), "+f"(d[1]), "+f"(d[2]), "+f"(d[3])
        : "r"(a[0]), "r"(a[1]), "r"(a[2]), "r"(a[3]), "r"(b[0]), "r"(b[1]));
}

template <int TRANS>
__global__ __launch_bounds__(256, 2)
void gemm_tf32(const float* __restrict__ Ag, const float* __restrict__ Bg,
               float* __restrict__ Cg, int M, int N, int K,
               size_t sA, size_t sB, size_t sC, float alpha,
               const float* __restrict__ bias, const float* __restrict__ res)
{
    extern __shared__ float smem[];
    const int tid = threadIdx.x;
    const int bm = blockIdx.y * BM;
    const int bn = blockIdx.x * BN;
    const float* A = Ag + blockIdx.z * sA;
    const float* B = Bg + blockIdx.z * sB;
    float* C = Cg + blockIdx.z * sC;
    const float* R = res ? res + blockIdx.z * sC : nullptr;

    const int lane = tid & 31;
    const int warp = tid >> 5;
    const int wm   = (warp >> 2) << 6;  // 0 / 64
    const int wn   = (warp & 3) << 5;   // 0..96
    const int gid  = lane >> 2;         // 0..7
    const int tig  = lane & 3;          // 0..3

    float acc[4][4][4];
    #pragma unroll
    for (int i = 0; i < 4; i++)
        #pragma unroll
        for (int j = 0; j < 4; j++)
            #pragma unroll
            for (int r = 0; r < 4; r++) acc[i][j][r] = 0.f;

    // tile loader: stage s, k offset k0
    auto load_tiles = [&](int k0, int s) {
        float* As = smem + s * TILEF;
        float* Bs = smem + 2 * TILEF + s * TILEF;
        #pragma unroll
        for (int i = 0; i < 4; i++) {
            int id  = tid + i * 256;
            int row = id >> 3;
            int cof = (id & 7) << 2;    // float offset into 32
            uint32_t da = (uint32_t)__cvta_generic_to_shared(As + row * ROWF + cof);
            const float* ga = A + (size_t)(bm + row) * K + k0 + cof;
            asm volatile("cp.async.cg.shared.global [%0], [%1], 16;" :: "r"(da), "l"(ga));
            uint32_t db = (uint32_t)__cvta_generic_to_shared(Bs + row * ROWF + cof);
            const float* gb = B + (size_t)(bn + row) * K + k0 + cof;
            asm volatile("cp.async.cg.shared.global [%0], [%1], 16;" :: "r"(db), "l"(gb));
        }
    };

    const int kIter = K >> 5;
    load_tiles(0, 0);
    asm volatile("cp.async.commit_group;");

    int s = 0;
    for (int it = 0; it < kIter; it++) {
        if (it + 1 < kIter) {
            load_tiles((it + 1) << 5, s ^ 1);
            asm volatile("cp.async.commit_group;");
            asm volatile("cp.async.wait_group 1;");
        } else {
            asm volatile("cp.async.wait_group 0;");
        }
        __syncthreads();

        const float* As = smem + s * TILEF;
        const float* Bs = smem + 2 * TILEF + s * TILEF;
        #pragma unroll
        for (int ks = 0; ks < 4; ks++) {
            uint32_t a[4][4], b[4][2];
            const int col = (ks << 3) + tig;
            #pragma unroll
            for (int mt = 0; mt < 4; mt++) {
                const float* p = As + (wm + mt * 16 + gid) * ROWF + col;
                a[mt][0] = f2tf(p[0]);
                a[mt][1] = f2tf(p[8 * ROWF]);
                a[mt][2] = f2tf(p[4]);
                a[mt][3] = f2tf(p[8 * ROWF + 4]);
            }
            #pragma unroll
            for (int nt = 0; nt < 4; nt++) {
                const float* p = Bs + (wn + nt * 8 + gid) * ROWF + col;
                b[nt][0] = f2tf(p[0]);
                b[nt][1] = f2tf(p[4]);
            }
            #pragma unroll
            for (int mt = 0; mt < 4; mt++)
                #pragma unroll
                for (int nt = 0; nt < 4; nt++)
                    mma_tf32(acc[mt][nt], a[mt], b[nt]);
        }
        __syncthreads();
        s ^= 1;
    }

    // epilogue
    #pragma unroll
    for (int mt = 0; mt < 4; mt++) {
        #pragma unroll
        for (int nt = 0; nt < 4; nt++) {
            int m0 = bm + wm + mt * 16 + gid;
            int n0 = bn + wn + nt * 8 + 2 * tig;
            float d0 = acc[mt][nt][0] * alpha;
            float d1 = acc[mt][nt][1] * alpha;
            float d2 = acc[mt][nt][2] * alpha;
            float d3 = acc[mt][nt][3] * alpha;
            if (bias) {
                float b0 = bias[n0], b1 = bias[n0 + 1];
                d0 += b0; d1 += b1; d2 += b0; d3 += b1;
            }
            if (TRANS) {
                size_t i00 = (size_t)n0 * M + m0;        // ldc = M
                size_t i10 = i00 + M;                    // n0+1
                if (R) {
                    d0 += R[i00]; d1 += R[i10];
                    d2 += R[i00 + 8]; d3 += R[i10 + 8];
                }
                C[i00]     = d0; C[i10]     = d1;
                C[i00 + 8] = d2; C[i10 + 8] = d3;
            } else {
                float2 v0 = make_float2(d0, d1);
                float2 v1 = make_float2(d2, d3);
                *(float2*)&C[(size_t)m0 * N + n0]       = v0;
                *(float2*)&C[(size_t)(m0 + 8) * N + n0] = v1;
            }
        }
    }
}

// ---------------- row softmax (row of 4096, register-resident) ----------------
__global__ __launch_bounds__(256) void softmax_kernel(float* __restrict__ s)
{
    float4* row = (float4*)(s + (size_t)blockIdx.x * L_DIM);
    __shared__ float red[256];
    const int tid = threadIdx.x;

    float4 v[4];
    float m = -1e30f;
    #pragma unroll
    for (int j = 0; j < 4; j++) {
        v[j] = row[tid + j * 256];
        m = fmaxf(m, fmaxf(fmaxf(v[j].x, v[j].y), fmaxf(v[j].z, v[j].w)));
    }
    red[tid] = m; __syncthreads();
    for (int st = 128; st > 0; st >>= 1) {
        if (tid < st) red[tid] = fmaxf(red[tid], red[tid + st]);
        __syncthreads();
    }
    m = red[0]; __syncthreads();

    float sum = 0.f;
    #pragma unroll
    for (int j = 0; j < 4; j++) {
        v[j].x = __expf(v[j].x - m);
        v[j].y = __expf(v[j].y - m);
        v[j].z = __expf(v[j].z - m);
        v[j].w = __expf(v[j].w - m);
        sum += v[j].x + v[j].y + v[j].z + v[j].w;
    }
    red[tid] = sum; __syncthreads();
    for (int st = 128; st > 0; st >>= 1) {
        if (tid < st) red[tid] += red[tid + st];
        __syncthreads();
    }
    const float inv = 1.f / red[0];
    #pragma unroll
    for (int j = 0; j < 4; j++) {
        v[j].x *= inv; v[j].y *= inv; v[j].z *= inv; v[j].w *= inv;
        row[tid + j * 256] = v[j];
    }
}

// ---------------- host launch ----------------
extern "C" void kernel_launch(void* const* d_in, const int* in_sizes, int n_in,
                              void* d_out, int out_size)
{
    const float* x        = (const float*)d_in[0];
    const float* gn_scale = (const float*)d_in[1];
    const float* gn_bias  = (const float*)d_in[2];
    const float* wq = (const float*)d_in[3];
    const float* bq = (const float*)d_in[4];
    const float* wk = (const float*)d_in[5];
    const float* bk = (const float*)d_in[6];
    const float* wv = (const float*)d_in[7];
    const float* bv = (const float*)d_in[8];
    const float* wo = (const float*)d_in[9];
    const float* bo = (const float*)d_in[10];
    float* out = (float*)d_out;

    static float *p_ht = nullptr, *p_q = nullptr, *p_k = nullptr,
                 *p_v = nullptr, *p_o = nullptr, *p_s = nullptr;
    if (!p_ht) {
        cudaGetSymbolAddress((void**)&p_ht, g_ht);
        cudaGetSymbolAddress((void**)&p_q, g_q);
        cudaGetSymbolAddress((void**)&p_k, g_k);
        cudaGetSymbolAddress((void**)&p_v, g_v);
        cudaGetSymbolAddress((void**)&p_o, g_o);
        cudaGetSymbolAddress((void**)&p_s, g_s);
        cudaFuncSetAttribute(gemm_tf32<0>, cudaFuncAttributeMaxDynamicSharedMemorySize, SMEM_BYTES);
        cudaFuncSetAttribute(gemm_tf32<1>, cudaFuncAttributeMaxDynamicSharedMemorySize, SMEM_BYTES);
    }

    const float att_scale = 0.044194173824159216f;  // 512^-0.5

    // 1. GroupNorm -> h_t [L, C]
    gn_kernel<<<N_BATCH * NGROUP, 256>>>(x, gn_scale, gn_bias, p_ht);

    // 2. QKV: [L,C] = h_t[L,C] x w[C,C]^T  (v stored transposed as [C, L])
    dim3 gq(C_DIM / BN, L_DIM / BM, N_BATCH);  // (4, 32, 4)
    gemm_tf32<0><<<gq, 256, SMEM_BYTES>>>(p_ht, wq, p_q, L_DIM, C_DIM, C_DIM,
                                          CL, 0, CL, 1.f, bq, nullptr);
    gemm_tf32<0><<<gq, 256, SMEM_BYTES>>>(p_ht, wk, p_k, L_DIM, C_DIM, C_DIM,
                                          CL, 0, CL, 1.f, bk, nullptr);
    gemm_tf32<1><<<gq, 256, SMEM_BYTES>>>(p_ht, wv, p_v, L_DIM, C_DIM, C_DIM,
                                          CL, 0, CL, 1.f, bv, nullptr);

    // 3. scores = q_t x k_t^T * scale : [L, L]
    dim3 gs(L_DIM / BN, L_DIM / BM, N_BATCH);  // (32, 32, 4)
    gemm_tf32<0><<<gs, 256, SMEM_BYTES>>>(p_q, p_k, p_s, L_DIM, L_DIM, C_DIM,
                                          CL, CL, LL, att_scale, nullptr, nullptr);

    // 4. softmax rows
    softmax_kernel<<<N_BATCH * L_DIM, 256>>>(p_s);

    // 5. O_t[L, C] = att[L, L] x v[C, L]^T
    gemm_tf32<0><<<gq, 256, SMEM_BYTES>>>(p_s, p_v, p_o, L_DIM, C_DIM, L_DIM,
                                          LL, CL, CL, 1.f, nullptr, nullptr);

    // 6. out[C, L] = (O_t x wo^T)^T + bo + x   (transposed store + residual)
    gemm_tf32<1><<<gq, 256, SMEM_BYTES>>>(p_o, wo, out, L_DIM, C_DIM, C_DIM,
                                          CL, 0, CL, 1.f, bo, x);
}

// round 3
// speedup vs baseline: 7.5389x; 1.8624x over previous
#include <cuda_runtime.h>
#include <cuda_bf16.h>
#include <math.h>
#include <stdint.h>

#define N_BATCH 4
#define C_DIM   512
#define L_DIM   4096
#define NGROUP  32
#define CPG     16
#define GN_EPS  1e-5f
#define CL      ((size_t)C_DIM * L_DIM)
#define LL      ((size_t)L_DIM * L_DIM)

typedef __nv_bfloat16 bf16;

// ---------------- scratch ----------------
__device__ bf16  g_ht[N_BATCH * CL];   // groupnorm output [L, C] bf16
__device__ bf16  g_q [N_BATCH * CL];   // [L, C]
__device__ bf16  g_k [N_BATCH * CL];   // [L, C]
__device__ bf16  g_v [N_BATCH * CL];   // [C, L]
__device__ bf16  g_o [N_BATCH * CL];   // att @ v, [L, C]
__device__ float g_s [N_BATCH * LL];   // raw scores fp32
__device__ bf16  g_p [N_BATCH * LL];   // softmax probs bf16
__device__ bf16  g_wq[C_DIM * C_DIM];
__device__ bf16  g_wk[C_DIM * C_DIM];
__device__ bf16  g_wv[C_DIM * C_DIM];
__device__ bf16  g_wo[C_DIM * C_DIM];

// ---------------- weight fp32 -> bf16 prep ----------------
__global__ void cvt_w_kernel(const float* __restrict__ wq, const float* __restrict__ wk,
                             const float* __restrict__ wv, const float* __restrict__ wo)
{
    int i = blockIdx.x * 256 + threadIdx.x;
    g_wq[i] = __float2bfloat16(wq[i]);
    g_wk[i] = __float2bfloat16(wk[i]);
    g_wv[i] = __float2bfloat16(wv[i]);
    g_wo[i] = __float2bfloat16(wo[i]);
}

// ---------------- GroupNorm -> transposed bf16 output h_t[L, C] ----------------
__global__ __launch_bounds__(256) void gn_kernel(const float* __restrict__ x,
                                                 const float* __restrict__ scale,
                                                 const float* __restrict__ bias,
                                                 bf16* __restrict__ ht)
{
    const int n = blockIdx.x >> 5;
    const int g = blockIdx.x & 31;
    const float* __restrict__ xg = x + ((size_t)n * C_DIM + (size_t)g * CPG) * L_DIM;
    bf16* __restrict__ hb = ht + (size_t)n * CL + g * CPG;
    const int tid = threadIdx.x;

    const float4* xv = (const float4*)xg;
    float s = 0.f, ss = 0.f;
    for (int i = tid; i < CPG * L_DIM / 4; i += 256) {
        float4 v = xv[i];
        s  += v.x + v.y + v.z + v.w;
        ss += v.x*v.x + v.y*v.y + v.z*v.z + v.w*v.w;
    }
    __shared__ float rs[256], rss[256];
    rs[tid] = s; rss[tid] = ss;
    __syncthreads();
    for (int st = 128; st > 0; st >>= 1) {
        if (tid < st) { rs[tid] += rs[tid+st]; rss[tid] += rss[tid+st]; }
        __syncthreads();
    }
    const float inv_n = 1.f / (float)(CPG * L_DIM);
    const float mean = rs[0] * inv_n;
    const float var  = rss[0] * inv_n - mean * mean;
    const float rstd = rsqrtf(var + GN_EPS);

    __shared__ float tile[16][260];
    for (int l0 = 0; l0 < L_DIM; l0 += 256) {
        #pragma unroll
        for (int j = 0; j < 4; j++) {
            int vi = tid + j * 256;
            int c  = vi >> 6;
            int lv = vi & 63;
            float4 v = xv[c * (L_DIM/4) + (l0 >> 2) + lv];
            float sc = scale[g*CPG + c] * rstd;
            float bi = bias[g*CPG + c] - mean * sc;
            tile[c][4*lv+0] = v.x*sc + bi;
            tile[c][4*lv+1] = v.y*sc + bi;
            tile[c][4*lv+2] = v.z*sc + bi;
            tile[c][4*lv+3] = v.w*sc + bi;
        }
        __syncthreads();
        #pragma unroll
        for (int j = 0; j < 4; j++) {
            int vi = tid + j * 256;
            int l  = vi >> 2;
            int c4 = vi & 3;
            __nv_bfloat162 p0 = __floats2bfloat162_rn(tile[4*c4+0][l], tile[4*c4+1][l]);
            __nv_bfloat162 p1 = __floats2bfloat162_rn(tile[4*c4+2][l], tile[4*c4+3][l]);
            bf16* dst = hb + (size_t)(l0 + l) * C_DIM + 4*c4;
            *(__nv_bfloat162*)(dst)     = p0;
            *(__nv_bfloat162*)(dst + 2) = p1;
        }
        __syncthreads();
    }
}

// ---------------- bf16 MMA NT-GEMM ----------------
// C[M,N] = alpha * A[M,K] * B[N,K]^T (+bias[n]) (+res); A,B K-major bf16.
// MODE 0: bf16 store row-major     (q, k, o)
// MODE 1: bf16 store transposed    (v)
// MODE 2: fp32 store row-major     (scores)
// MODE 3: fp32 store transposed + bias + residual (final out)
#define BM 128
#define BN 128
#define BK 64
#define PITCH 72                       // bf16 elems per smem row (conflict-free)
#define TILEE (128 * PITCH)            // 9216 bf16
#define SMEM_BYTES (4 * TILEE * 2)     // 73728 B

__device__ __forceinline__ void mma_bf16(float* d, const uint32_t* a, const uint32_t* b) {
    asm volatile(
        "mma.sync.aligned.m16n8k16.row.col.f32.bf16.bf16.f32 "
        "{%0,%1,%2,%3},{%4,%5,%6,%7},{%8,%9},{%0,%1,%2,%3};"
        : "+f"(d[0]), "+f"(d[1]), "+f"(d[2]), "+f"(d[3])
        : "r"(a[0]), "r"(a[1]), "r"(a[2]), "r"(a[3]), "r"(b[0]), "r"(b[1]));
}

template <int MODE>
__global__ __launch_bounds__(256, 2)
void gemm_bf16(const bf16* __restrict__ Ag, const bf16* __restrict__ Bg,
               void* __restrict__ Cg, int M, int N, int K,
               size_t sA, size_t sB, size_t sC, float alpha,
               const float* __restrict__ bias, const float* __restrict__ res)
{
    extern __shared__ bf16 sm[];
    const int tid = threadIdx.x;
    const int bm = blockIdx.y * BM;
    const int bn = blockIdx.x * BN;
    const bf16* A = Ag + blockIdx.z * sA;
    const bf16* B = Bg + blockIdx.z * sB;
    const float* R = res ? res + blockIdx.z * sC : nullptr;

    const int lane = tid & 31;
    const int warp = tid >> 5;
    const int wm   = (warp >> 2) << 6;  // 0 / 64
    const int wn   = (warp & 3) << 5;   // 0..96
    const int gid  = lane >> 2;
    const int tig  = lane & 3;

    float acc[4][4][4];
    #pragma unroll
    for (int i = 0; i < 4; i++)
        #pragma unroll
        for (int j = 0; j < 4; j++)
            #pragma unroll
            for (int r = 0; r < 4; r++) acc[i][j][r] = 0.f;

    auto load_tiles = [&](int k0, int s) {
        bf16* As = sm + s * TILEE;
        bf16* Bs = sm + 2 * TILEE + s * TILEE;
        #pragma unroll
        for (int i = 0; i < 4; i++) {
            int id  = tid + i * 256;
            int row = id >> 3;
            int cof = (id & 7) << 3;    // bf16 offset (8 bf16 = 16B)
            uint32_t da = (uint32_t)__cvta_generic_to_shared(As + row * PITCH + cof);
            const bf16* ga = A + (size_t)(bm + row) * K + k0 + cof;
            asm volatile("cp.async.cg.shared.global [%0], [%1], 16;" :: "r"(da), "l"(ga));
            uint32_t db = (uint32_t)__cvta_generic_to_shared(Bs + row * PITCH + cof);
            const bf16* gb = B + (size_t)(bn + row) * K + k0 + cof;
            asm volatile("cp.async.cg.shared.global [%0], [%1], 16;" :: "r"(db), "l"(gb));
        }
    };

    const int kIter = K >> 6;
    load_tiles(0, 0);
    asm volatile("cp.async.commit_group;");

    int s = 0;
    for (int it = 0; it < kIter; it++) {
        if (it + 1 < kIter) {
            load_tiles((it + 1) << 6, s ^ 1);
            asm volatile("cp.async.commit_group;");
            asm volatile("cp.async.wait_group 1;");
        } else {
            asm volatile("cp.async.wait_group 0;");
        }
        __syncthreads();

        const bf16* As = sm + s * TILEE;
        const bf16* Bs = sm + 2 * TILEE + s * TILEE;
        #pragma unroll
        for (int ks = 0; ks < 4; ks++) {
            const int col = (ks << 4) + (tig << 1);
            uint32_t a[4][4], b[4][2];
            #pragma unroll
            for (int mt = 0; mt < 4; mt++) {
                const bf16* p = As + (wm + mt * 16 + gid) * PITCH + col;
                a[mt][0] = *(const uint32_t*)(p);
                a[mt][1] = *(const uint32_t*)(p + 8 * PITCH);
                a[mt][2] = *(const uint32_t*)(p + 8);
                a[mt][3] = *(const uint32_t*)(p + 8 * PITCH + 8);
            }
            #pragma unroll
            for (int nt = 0; nt < 4; nt++) {
                const bf16* p = Bs + (wn + nt * 8 + gid) * PITCH + col;
                b[nt][0] = *(const uint32_t*)(p);
                b[nt][1] = *(const uint32_t*)(p + 8);
            }
            #pragma unroll
            for (int mt = 0; mt < 4; mt++)
                #pragma unroll
                for (int nt = 0; nt < 4; nt++)
                    mma_bf16(acc[mt][nt], a[mt], b[nt]);
        }
        __syncthreads();
        s ^= 1;
    }

    // epilogue
    #pragma unroll
    for (int mt = 0; mt < 4; mt++) {
        #pragma unroll
        for (int nt = 0; nt < 4; nt++) {
            int m0 = bm + wm + mt * 16 + gid;
            int n0 = bn + wn + nt * 8 + 2 * tig;
            float d0 = acc[mt][nt][0] * alpha;
            float d1 = acc[mt][nt][1] * alpha;
            float d2 = acc[mt][nt][2] * alpha;
            float d3 = acc[mt][nt][3] * alpha;
            if (bias) {
                float b0 = bias[n0], b1 = bias[n0 + 1];
                d0 += b0; d1 += b1; d2 += b0; d3 += b1;
            }
            if (MODE == 0) {
                bf16* C = (bf16*)Cg + blockIdx.z * sC;
                *(__nv_bfloat162*)&C[(size_t)m0 * N + n0]       = __floats2bfloat162_rn(d0, d1);
                *(__nv_bfloat162*)&C[(size_t)(m0 + 8) * N + n0] = __floats2bfloat162_rn(d2, d3);
            } else if (MODE == 1) {
                bf16* C = (bf16*)Cg + blockIdx.z * sC;
                size_t i0 = (size_t)n0 * M + m0;
                C[i0]         = __float2bfloat16(d0);
                C[i0 + M]     = __float2bfloat16(d1);
                C[i0 + 8]     = __float2bfloat16(d2);
                C[i0 + M + 8] = __float2bfloat16(d3);
            } else if (MODE == 2) {
                float* C = (float*)Cg + blockIdx.z * sC;
                *(float2*)&C[(size_t)m0 * N + n0]       = make_float2(d0, d1);
                *(float2*)&C[(size_t)(m0 + 8) * N + n0] = make_float2(d2, d3);
            } else {
                float* C = (float*)Cg + blockIdx.z * sC;
                size_t i00 = (size_t)n0 * M + m0;
                size_t i10 = i00 + M;
                if (R) {
                    d0 += R[i00]; d1 += R[i10];
                    d2 += R[i00 + 8]; d3 += R[i10 + 8];
                }
                C[i00]     = d0; C[i10]     = d1;
                C[i00 + 8] = d2; C[i10 + 8] = d3;
            }
        }
    }
}

// ---------------- row softmax: fp32 in, bf16 out ----------------
__global__ __launch_bounds__(256) void softmax_kernel(const float* __restrict__ s,
                                                      bf16* __restrict__ p)
{
    const float4* row = (const float4*)(s + (size_t)blockIdx.x * L_DIM);
    bf16* prow = p + (size_t)blockIdx.x * L_DIM;
    __shared__ float red[256];
    const int tid = threadIdx.x;

    float4 v[4];
    float m = -1e30f;
    #pragma unroll
    for (int j = 0; j < 4; j++) {
        v[j] = row[tid + j * 256];
        m = fmaxf(m, fmaxf(fmaxf(v[j].x, v[j].y), fmaxf(v[j].z, v[j].w)));
    }
    red[tid] = m; __syncthreads();
    for (int st = 128; st > 0; st >>= 1) {
        if (tid < st) red[tid] = fmaxf(red[tid], red[tid + st]);
        __syncthreads();
    }
    m = red[0]; __syncthreads();

    float sum = 0.f;
    #pragma unroll
    for (int j = 0; j < 4; j++) {
        v[j].x = __expf(v[j].x - m);
        v[j].y = __expf(v[j].y - m);
        v[j].z = __expf(v[j].z - m);
        v[j].w = __expf(v[j].w - m);
        sum += v[j].x + v[j].y + v[j].z + v[j].w;
    }
    red[tid] = sum; __syncthreads();
    for (int st = 128; st > 0; st >>= 1) {
        if (tid < st) red[tid] += red[tid + st];
        __syncthreads();
    }
    const float inv = 1.f / red[0];
    #pragma unroll
    for (int j = 0; j < 4; j++) {
        int e = (tid + j * 256) * 4;
        *(__nv_bfloat162*)&prow[e]     = __floats2bfloat162_rn(v[j].x * inv, v[j].y * inv);
        *(__nv_bfloat162*)&prow[e + 2] = __floats2bfloat162_rn(v[j].z * inv, v[j].w * inv);
    }
}

// ---------------- host launch ----------------
extern "C" void kernel_launch(void* const* d_in, const int* in_sizes, int n_in,
                              void* d_out, int out_size)
{
    const float* x        = (const float*)d_in[0];
    const float* gn_scale = (const float*)d_in[1];
    const float* gn_bias  = (const float*)d_in[2];
    const float* wq = (const float*)d_in[3];
    const float* bq = (const float*)d_in[4];
    const float* wk = (const float*)d_in[5];
    const float* bk = (const float*)d_in[6];
    const float* wv = (const float*)d_in[7];
    const float* bv = (const float*)d_in[8];
    const float* wo = (const float*)d_in[9];
    const float* bo = (const float*)d_in[10];
    float* out = (float*)d_out;

    static bf16 *p_ht=nullptr, *p_q=nullptr, *p_k=nullptr, *p_v=nullptr,
                *p_o=nullptr, *p_p=nullptr;
    static float *p_s=nullptr;
    static bf16 *p_wq=nullptr, *p_wk=nullptr, *p_wv=nullptr, *p_wo=nullptr;
    if (!p_ht) {
        cudaGetSymbolAddress((void**)&p_ht, g_ht);
        cudaGetSymbolAddress((void**)&p_q,  g_q);
        cudaGetSymbolAddress((void**)&p_k,  g_k);
        cudaGetSymbolAddress((void**)&p_v,  g_v);
        cudaGetSymbolAddress((void**)&p_o,  g_o);
        cudaGetSymbolAddress((void**)&p_s,  g_s);
        cudaGetSymbolAddress((void**)&p_p,  g_p);
        cudaGetSymbolAddress((void**)&p_wq, g_wq);
        cudaGetSymbolAddress((void**)&p_wk, g_wk);
        cudaGetSymbolAddress((void**)&p_wv, g_wv);
        cudaGetSymbolAddress((void**)&p_wo, g_wo);
        cudaFuncSetAttribute(gemm_bf16<0>, cudaFuncAttributeMaxDynamicSharedMemorySize, SMEM_BYTES);
        cudaFuncSetAttribute(gemm_bf16<1>, cudaFuncAttributeMaxDynamicSharedMemorySize, SMEM_BYTES);
        cudaFuncSetAttribute(gemm_bf16<2>, cudaFuncAttributeMaxDynamicSharedMemorySize, SMEM_BYTES);
        cudaFuncSetAttribute(gemm_bf16<3>, cudaFuncAttributeMaxDynamicSharedMemorySize, SMEM_BYTES);
    }

    const float att_scale = 0.044194173824159216f;  // 512^-0.5

    // 0. weights -> bf16
    cvt_w_kernel<<<(C_DIM * C_DIM) / 256, 256>>>(wq, wk, wv, wo);

    // 1. GroupNorm -> h_t [L, C] bf16
    gn_kernel<<<N_BATCH * NGROUP, 256>>>(x, gn_scale, gn_bias, p_ht);

    // 2. QKV
    dim3 gq(C_DIM / BN, L_DIM / BM, N_BATCH);
    gemm_bf16<0><<<gq, 256, SMEM_BYTES>>>(p_ht, p_wq, p_q, L_DIM, C_DIM, C_DIM,
                                          CL, 0, CL, 1.f, bq, nullptr);
    gemm_bf16<0><<<gq, 256, SMEM_BYTES>>>(p_ht, p_wk, p_k, L_DIM, C_DIM, C_DIM,
                                          CL, 0, CL, 1.f, bk, nullptr);
    gemm_bf16<1><<<gq, 256, SMEM_BYTES>>>(p_ht, p_wv, p_v, L_DIM, C_DIM, C_DIM,
                                          CL, 0, CL, 1.f, bv, nullptr);

    // 3. scores fp32 = q k^T * scale
    dim3 gs(L_DIM / BN, L_DIM / BM, N_BATCH);
    gemm_bf16<2><<<gs, 256, SMEM_BYTES>>>(p_q, p_k, p_s, L_DIM, L_DIM, C_DIM,
                                          CL, CL, LL, att_scale, nullptr, nullptr);

    // 4. softmax -> probs bf16
    softmax_kernel<<<N_BATCH * L_DIM, 256>>>(p_s, p_p);

    // 5. O_t[L, C] = probs x v^T
    gemm_bf16<0><<<gq, 256, SMEM_BYTES>>>(p_p, p_v, p_o, L_DIM, C_DIM, L_DIM,
                                          LL, CL, CL, 1.f, nullptr, nullptr);

    // 6. out[C, L] = (O_t x wo^T)^T + bo + x
    gemm_bf16<3><<<gq, 256, SMEM_BYTES>>>(p_o, p_wo, out, L_DIM, C_DIM, C_DIM,
                                          CL, 0, CL, 1.f, bo, x);
}

// round 4
// speedup vs baseline: 8.4234x; 1.1173x over previous
#include <cuda_runtime.h>
#include <cuda_bf16.h>
#include <math.h>
#include <stdint.h>

#define N_BATCH 4
#define C_DIM   512
#define L_DIM   4096
#define NGROUP  32
#define CPG     16
#define GN_EPS  1e-5f
#define CL      ((size_t)C_DIM * L_DIM)
#define LL      ((size_t)L_DIM * L_DIM)

typedef __nv_bfloat16 bf16;

// ---------------- scratch ----------------
__device__ bf16  g_ht[N_BATCH * CL];
__device__ bf16  g_q [N_BATCH * CL];
__device__ bf16  g_k [N_BATCH * CL];
__device__ bf16  g_v [N_BATCH * CL];   // [C, L]
__device__ bf16  g_o [N_BATCH * CL];   // [L, C]
__device__ float g_s [N_BATCH * LL];
__device__ bf16  g_p [N_BATCH * LL];
__device__ bf16  g_wq[C_DIM * C_DIM];
__device__ bf16  g_wk[C_DIM * C_DIM];
__device__ bf16  g_wv[C_DIM * C_DIM];
__device__ bf16  g_wo[C_DIM * C_DIM];

__global__ void cvt_w_kernel(const float* __restrict__ wq, const float* __restrict__ wk,
                             const float* __restrict__ wv, const float* __restrict__ wo)
{
    int i = blockIdx.x * 256 + threadIdx.x;
    g_wq[i] = __float2bfloat16(wq[i]);
    g_wk[i] = __float2bfloat16(wk[i]);
    g_wv[i] = __float2bfloat16(wv[i]);
    g_wo[i] = __float2bfloat16(wo[i]);
}

// ---------------- GroupNorm -> h_t[L, C] bf16 ----------------
__global__ __launch_bounds__(256) void gn_kernel(const float* __restrict__ x,
                                                 const float* __restrict__ scale,
                                                 const float* __restrict__ bias,
                                                 bf16* __restrict__ ht)
{
    const int n = blockIdx.x >> 5;
    const int g = blockIdx.x & 31;
    const float* __restrict__ xg = x + ((size_t)n * C_DIM + (size_t)g * CPG) * L_DIM;
    bf16* __restrict__ hb = ht + (size_t)n * CL + g * CPG;
    const int tid = threadIdx.x;

    const float4* xv = (const float4*)xg;
    float s = 0.f, ss = 0.f;
    for (int i = tid; i < CPG * L_DIM / 4; i += 256) {
        float4 v = xv[i];
        s  += v.x + v.y + v.z + v.w;
        ss += v.x*v.x + v.y*v.y + v.z*v.z + v.w*v.w;
    }
    __shared__ float rs[256], rss[256];
    rs[tid] = s; rss[tid] = ss;
    __syncthreads();
    for (int st = 128; st > 0; st >>= 1) {
        if (tid < st) { rs[tid] += rs[tid+st]; rss[tid] += rss[tid+st]; }
        __syncthreads();
    }
    const float inv_n = 1.f / (float)(CPG * L_DIM);
    const float mean = rs[0] * inv_n;
    const float var  = rss[0] * inv_n - mean * mean;
    const float rstd = rsqrtf(var + GN_EPS);

    __shared__ float tile[16][260];
    for (int l0 = 0; l0 < L_DIM; l0 += 256) {
        #pragma unroll
        for (int j = 0; j < 4; j++) {
            int vi = tid + j * 256;
            int c  = vi >> 6;
            int lv = vi & 63;
            float4 v = xv[c * (L_DIM/4) + (l0 >> 2) + lv];
            float sc = scale[g*CPG + c] * rstd;
            float bi = bias[g*CPG + c] - mean * sc;
            tile[c][4*lv+0] = v.x*sc + bi;
            tile[c][4*lv+1] = v.y*sc + bi;
            tile[c][4*lv+2] = v.z*sc + bi;
            tile[c][4*lv+3] = v.w*sc + bi;
        }
        __syncthreads();
        #pragma unroll
        for (int j = 0; j < 4; j++) {
            int vi = tid + j * 256;
            int l  = vi >> 2;
            int c4 = vi & 3;
            __nv_bfloat162 p0 = __floats2bfloat162_rn(tile[4*c4+0][l], tile[4*c4+1][l]);
            __nv_bfloat162 p1 = __floats2bfloat162_rn(tile[4*c4+2][l], tile[4*c4+3][l]);
            bf16* dst = hb + (size_t)(l0 + l) * C_DIM + 4*c4;
            *(__nv_bfloat162*)(dst)     = p0;
            *(__nv_bfloat162*)(dst + 2) = p1;
        }
        __syncthreads();
    }
}

// ---------------- bf16 MMA NT-GEMM with ldmatrix ----------------
// MODE 0: bf16 row-major   MODE 1: bf16 transposed (smem-staged)
// MODE 2: fp32 row-major   MODE 3: fp32 transposed + residual (smem-staged)
#define BM 128
#define BN 128
#define BK 64
#define PITCH 72
#define TILEE (128 * PITCH)
#define SMEM_BYTES (4 * TILEE * 2)     // 73728 B

__device__ __forceinline__ void mma_bf16(float* d, const uint32_t* a, const uint32_t* b) {
    asm volatile(
        "mma.sync.aligned.m16n8k16.row.col.f32.bf16.bf16.f32 "
        "{%0,%1,%2,%3},{%4,%5,%6,%7},{%8,%9},{%0,%1,%2,%3};"
        : "+f"(d[0]), "+f"(d[1]), "+f"(d[2]), "+f"(d[3])
        : "r"(a[0]), "r"(a[1]), "r"(a[2]), "r"(a[3]), "r"(b[0]), "r"(b[1]));
}

__device__ __forceinline__ void ldsm_x4(uint32_t* r, uint32_t addr) {
    asm volatile("ldmatrix.sync.aligned.m8n8.x4.shared.b16 {%0,%1,%2,%3}, [%4];"
        : "=r"(r[0]), "=r"(r[1]), "=r"(r[2]), "=r"(r[3]) : "r"(addr));
}

template <int MODE>
__global__ __launch_bounds__(256, 2)
void gemm_bf16(const bf16* __restrict__ Ag, const bf16* __restrict__ Bg,
               void* __restrict__ Cg, int M, int N, int K,
               size_t sA, size_t sB, size_t sC, float alpha,
               const float* __restrict__ bias, const float* __restrict__ res)
{
    extern __shared__ bf16 sm[];
    const int tid = threadIdx.x;
    const int bm = blockIdx.y * BM;
    const int bn = blockIdx.x * BN;
    const bf16* A = Ag + blockIdx.z * sA;
    const bf16* B = Bg + blockIdx.z * sB;
    const float* R = res ? res + blockIdx.z * sC : nullptr;

    const int lane = tid & 31;
    const int warp = tid >> 5;
    const int wm   = (warp >> 2) << 6;
    const int wn   = (warp & 3) << 5;
    const int gid  = lane >> 2;
    const int tig  = lane & 3;

    const uint32_t smem_u = (uint32_t)__cvta_generic_to_shared(sm);
    // ldmatrix lane->address offsets (bytes)
    const uint32_t a_off = ((wm + (lane & 15)) * PITCH + ((lane >> 4) << 3)) * 2;
    const uint32_t b_off = ((wn + (lane & 7) + ((lane >> 4) << 3)) * PITCH
                            + (((lane >> 3) & 1) << 3)) * 2;

    float acc[4][4][4];
    #pragma unroll
    for (int i = 0; i < 4; i++)
        #pragma unroll
        for (int j = 0; j < 4; j++)
            #pragma unroll
            for (int r = 0; r < 4; r++) acc[i][j][r] = 0.f;

    auto load_tiles = [&](int k0, int s) {
        bf16* As = sm + s * TILEE;
        bf16* Bs = sm + (2 + s) * TILEE;
        #pragma unroll
        for (int i = 0; i < 4; i++) {
            int id  = tid + i * 256;
            int row = id >> 3;
            int cof = (id & 7) << 3;
            uint32_t da = (uint32_t)__cvta_generic_to_shared(As + row * PITCH + cof);
            const bf16* ga = A + (size_t)(bm + row) * K + k0 + cof;
            asm volatile("cp.async.cg.shared.global [%0], [%1], 16;" :: "r"(da), "l"(ga));
            uint32_t db = (uint32_t)__cvta_generic_to_shared(Bs + row * PITCH + cof);
            const bf16* gb = B + (size_t)(bn + row) * K + k0 + cof;
            asm volatile("cp.async.cg.shared.global [%0], [%1], 16;" :: "r"(db), "l"(gb));
        }
    };

    const int kIter = K >> 6;
    load_tiles(0, 0);
    asm volatile("cp.async.commit_group;");

    int s = 0;
    for (int it = 0; it < kIter; it++) {
        asm volatile("cp.async.wait_group 0;");
        __syncthreads();
        if (it + 1 < kIter) {
            load_tiles((it + 1) << 6, s ^ 1);
            asm volatile("cp.async.commit_group;");
        }

        const uint32_t As_u = smem_u + s * (TILEE * 2);
        const uint32_t Bs_u = smem_u + (2 + s) * (TILEE * 2);
        #pragma unroll
        for (int ks = 0; ks < 4; ks++) {
            const uint32_t kadd = ks * 32;   // 16 bf16 = 32 bytes
            uint32_t a[4][4], b[4][2];
            #pragma unroll
            for (int mt = 0; mt < 4; mt++)
                ldsm_x4(a[mt], As_u + a_off + mt * (16 * PITCH * 2) + kadd);
            #pragma unroll
            for (int p = 0; p < 2; p++) {
                uint32_t r[4];
                ldsm_x4(r, Bs_u + b_off + p * (16 * PITCH * 2) + kadd);
                b[2*p][0]   = r[0]; b[2*p][1]   = r[1];
                b[2*p+1][0] = r[2]; b[2*p+1][1] = r[3];
            }
            #pragma unroll
            for (int mt = 0; mt < 4; mt++)
                #pragma unroll
                for (int nt = 0; nt < 4; nt++)
                    mma_bf16(acc[mt][nt], a[mt], b[nt]);
        }
        s ^= 1;
    }

    // ---------------- epilogue ----------------
    if (MODE == 0 || MODE == 2) {
        #pragma unroll
        for (int mt = 0; mt < 4; mt++) {
            #pragma unroll
            for (int nt = 0; nt < 4; nt++) {
                int m0 = bm + wm + mt * 16 + gid;
                int n0 = bn + wn + nt * 8 + 2 * tig;
                float d0 = acc[mt][nt][0] * alpha;
                float d1 = acc[mt][nt][1] * alpha;
                float d2 = acc[mt][nt][2] * alpha;
                float d3 = acc[mt][nt][3] * alpha;
                if (bias) {
                    float b0 = bias[n0], b1 = bias[n0 + 1];
                    d0 += b0; d1 += b1; d2 += b0; d3 += b1;
                }
                if (MODE == 0) {
                    bf16* C = (bf16*)Cg + blockIdx.z * sC;
                    *(__nv_bfloat162*)&C[(size_t)m0 * N + n0]       = __floats2bfloat162_rn(d0, d1);
                    *(__nv_bfloat162*)&C[(size_t)(m0 + 8) * N + n0] = __floats2bfloat162_rn(d2, d3);
                } else {
                    float* C = (float*)Cg + blockIdx.z * sC;
                    *(float2*)&C[(size_t)m0 * N + n0]       = make_float2(d0, d1);
                    *(float2*)&C[(size_t)(m0 + 8) * N + n0] = make_float2(d2, d3);
                }
            }
        }
    } else if (MODE == 1) {
        // stage bf16 tile [n][m] in smem, pitch 136, then coalesced store
        bf16* smh = sm;
        __syncthreads();
        #pragma unroll
        for (int mt = 0; mt < 4; mt++) {
            #pragma unroll
            for (int nt = 0; nt < 4; nt++) {
                int ml = wm + mt * 16 + gid;
                int nl = wn + nt * 8 + 2 * tig;
                float d0 = acc[mt][nt][0], d1 = acc[mt][nt][1];
                float d2 = acc[mt][nt][2], d3 = acc[mt][nt][3];
                if (bias) {
                    int n0 = bn + nl;
                    float b0 = bias[n0], b1 = bias[n0 + 1];
                    d0 += b0; d1 += b1; d2 += b0; d3 += b1;
                }
                smh[nl * 136 + ml]           = __float2bfloat16(d0);
                smh[(nl + 1) * 136 + ml]     = __float2bfloat16(d1);
                smh[nl * 136 + ml + 8]       = __float2bfloat16(d2);
                smh[(nl + 1) * 136 + ml + 8] = __float2bfloat16(d3);
            }
        }
        __syncthreads();
        bf16* C = (bf16*)Cg + blockIdx.z * sC;
        #pragma unroll
        for (int i = 0; i < 8; i++) {
            int idx = tid + i * 256;
            int row = idx >> 4;
            int m = (idx & 15) << 3;
            uint4 v = *(uint4*)&smh[row * 136 + m];
            *(uint4*)&C[(size_t)(bn + row) * M + bm + m] = v;
        }
    } else {
        // MODE 3: stage fp32 tile [n][m], pitch 132, coalesced store + residual
        float* smf = (float*)sm;
        __syncthreads();
        #pragma unroll
        for (int mt = 0; mt < 4; mt++) {
            #pragma unroll
            for (int nt = 0; nt < 4; nt++) {
                int ml = wm + mt * 16 + gid;
                int nl = wn + nt * 8 + 2 * tig;
                float d0 = acc[mt][nt][0], d1 = acc[mt][nt][1];
                float d2 = acc[mt][nt][2], d3 = acc[mt][nt][3];
                if (bias) {
                    int n0 = bn + nl;
                    float b0 = bias[n0], b1 = bias[n0 + 1];
                    d0 += b0; d1 += b1; d2 += b0; d3 += b1;
                }
                smf[nl * 132 + ml]           = d0;
                smf[(nl + 1) * 132 + ml]     = d1;
                smf[nl * 132 + ml + 8]       = d2;
                smf[(nl + 1) * 132 + ml + 8] = d3;
            }
        }
        __syncthreads();
        float* C = (float*)Cg + blockIdx.z * sC;
        #pragma unroll
        for (int i = 0; i < 16; i++) {
            int idx = tid + i * 256;
            int row = idx >> 5;
            int m = (idx & 31) << 2;
            size_t gidx = (size_t)(bn + row) * M + bm + m;
            float4 v = *(float4*)&smf[row * 132 + m];
            if (R) {
                float4 r4 = *(const float4*)&R[gidx];
                v.x += r4.x; v.y += r4.y; v.z += r4.z; v.w += r4.w;
            }
            *(float4*)&C[gidx] = v;
        }
    }
}

// ---------------- row softmax: fp32 in, bf16 out ----------------
__global__ __launch_bounds__(256) void softmax_kernel(const float* __restrict__ s,
                                                      bf16* __restrict__ p)
{
    const float4* row = (const float4*)(s + (size_t)blockIdx.x * L_DIM);
    bf16* prow = p + (size_t)blockIdx.x * L_DIM;
    __shared__ float red[256];
    const int tid = threadIdx.x;

    float4 v[4];
    float m = -1e30f;
    #pragma unroll
    for (int j = 0; j < 4; j++) {
        v[j] = row[tid + j * 256];
        m = fmaxf(m, fmaxf(fmaxf(v[j].x, v[j].y), fmaxf(v[j].z, v[j].w)));
    }
    red[tid] = m; __syncthreads();
    for (int st = 128; st > 0; st >>= 1) {
        if (tid < st) red[tid] = fmaxf(red[tid], red[tid + st]);
        __syncthreads();
    }
    m = red[0]; __syncthreads();

    float sum = 0.f;
    #pragma unroll
    for (int j = 0; j < 4; j++) {
        v[j].x = __expf(v[j].x - m);
        v[j].y = __expf(v[j].y - m);
        v[j].z = __expf(v[j].z - m);
        v[j].w = __expf(v[j].w - m);
        sum += v[j].x + v[j].y + v[j].z + v[j].w;
    }
    red[tid] = sum; __syncthreads();
    for (int st = 128; st > 0; st >>= 1) {
        if (tid < st) red[tid] += red[tid + st];
        __syncthreads();
    }
    const float inv = 1.f / red[0];
    #pragma unroll
    for (int j = 0; j < 4; j++) {
        int e = (tid + j * 256) * 4;
        *(__nv_bfloat162*)&prow[e]     = __floats2bfloat162_rn(v[j].x * inv, v[j].y * inv);
        *(__nv_bfloat162*)&prow[e + 2] = __floats2bfloat162_rn(v[j].z * inv, v[j].w * inv);
    }
}

// ---------------- host launch ----------------
extern "C" void kernel_launch(void* const* d_in, const int* in_sizes, int n_in,
                              void* d_out, int out_size)
{
    const float* x        = (const float*)d_in[0];
    const float* gn_scale = (const float*)d_in[1];
    const float* gn_bias  = (const float*)d_in[2];
    const float* wq = (const float*)d_in[3];
    const float* bq = (const float*)d_in[4];
    const float* wk = (const float*)d_in[5];
    const float* bk = (const float*)d_in[6];
    const float* wv = (const float*)d_in[7];
    const float* bv = (const float*)d_in[8];
    const float* wo = (const float*)d_in[9];
    const float* bo = (const float*)d_in[10];
    float* out = (float*)d_out;

    static bf16 *p_ht=nullptr, *p_q=nullptr, *p_k=nullptr, *p_v=nullptr,
                *p_o=nullptr, *p_p=nullptr;
    static float *p_s=nullptr;
    static bf16 *p_wq=nullptr, *p_wk=nullptr, *p_wv=nullptr, *p_wo=nullptr;
    if (!p_ht) {
        cudaGetSymbolAddress((void**)&p_ht, g_ht);
        cudaGetSymbolAddress((void**)&p_q,  g_q);
        cudaGetSymbolAddress((void**)&p_k,  g_k);
        cudaGetSymbolAddress((void**)&p_v,  g_v);
        cudaGetSymbolAddress((void**)&p_o,  g_o);
        cudaGetSymbolAddress((void**)&p_s,  g_s);
        cudaGetSymbolAddress((void**)&p_p,  g_p);
        cudaGetSymbolAddress((void**)&p_wq, g_wq);
        cudaGetSymbolAddress((void**)&p_wk, g_wk);
        cudaGetSymbolAddress((void**)&p_wv, g_wv);
        cudaGetSymbolAddress((void**)&p_wo, g_wo);
        cudaFuncSetAttribute(gemm_bf16<0>, cudaFuncAttributeMaxDynamicSharedMemorySize, SMEM_BYTES);
        cudaFuncSetAttribute(gemm_bf16<1>, cudaFuncAttributeMaxDynamicSharedMemorySize, SMEM_BYTES);
        cudaFuncSetAttribute(gemm_bf16<2>, cudaFuncAttributeMaxDynamicSharedMemorySize, SMEM_BYTES);
        cudaFuncSetAttribute(gemm_bf16<3>, cudaFuncAttributeMaxDynamicSharedMemorySize, SMEM_BYTES);
    }

    const float att_scale = 0.044194173824159216f;

    cvt_w_kernel<<<(C_DIM * C_DIM) / 256, 256>>>(wq, wk, wv, wo);
    gn_kernel<<<N_BATCH * NGROUP, 256>>>(x, gn_scale, gn_bias, p_ht);

    dim3 gq(C_DIM / BN, L_DIM / BM, N_BATCH);
    gemm_bf16<0><<<gq, 256, SMEM_BYTES>>>(p_ht, p_wq, p_q, L_DIM, C_DIM, C_DIM,
                                          CL, 0, CL, 1.f, bq, nullptr);
    gemm_bf16<0><<<gq, 256, SMEM_BYTES>>>(p_ht, p_wk, p_k, L_DIM, C_DIM, C_DIM,
                                          CL, 0, CL, 1.f, bk, nullptr);
    gemm_bf16<1><<<gq, 256, SMEM_BYTES>>>(p_ht, p_wv, p_v, L_DIM, C_DIM, C_DIM,
                                          CL, 0, CL, 1.f, bv, nullptr);

    dim3 gs(L_DIM / BN, L_DIM / BM, N_BATCH);
    gemm_bf16<2><<<gs, 256, SMEM_BYTES>>>(p_q, p_k, p_s, L_DIM, L_DIM, C_DIM,
                                          CL, CL, LL, att_scale, nullptr, nullptr);

    softmax_kernel<<<N_BATCH * L_DIM, 256>>>(p_s, p_p);

    gemm_bf16<0><<<gq, 256, SMEM_BYTES>>>(p_p, p_v, p_o, L_DIM, C_DIM, L_DIM,
                                          LL, CL, CL, 1.f, nullptr, nullptr);

    gemm_bf16<3><<<gq, 256, SMEM_BYTES>>>(p_o, p_wo, out, L_DIM, C_DIM, C_DIM,
                                          CL, 0, CL, 1.f, bo, x);
}